// round 15
// baseline (speedup 1.0000x reference)
#include <cuda_runtime.h>
#include <cuda_bf16.h>
#include <cstdint>

#define NB 8
#define NT 2048
#define NC 1024
#define NH 64
#define NR (NB*NT)
#define SCALE_Q 0.18033688011112042f  // 0.125 * log2(e)

typedef uint32_t u32;

// bf16 hi/lo split planes + split-KV scratch (device globals: allocation-free)
__device__ u32 g_wh[192*NC/2], g_wl[192*NC/2];
__device__ u32 g_qh[NR*NH/2], g_ql[NR*NH/2];
__device__ u32 g_kh[NR*NH/2], g_kl[NR*NH/2];
__device__ u32 g_vh[NR*NH/2], g_vl[NR*NH/2];
__device__ float g_O0[NR*NH], g_O1[NR*NH];
__device__ float g_l0[NR], g_l1[NR];

// ---------------- helpers ----------------
__device__ __forceinline__ u32 s2u(const void* p){
    u32 a; asm("{ .reg .u64 t; cvta.to.shared.u64 t, %1; cvt.u32.u64 %0, t; }":"=r"(a):"l"(p)); return a;
}
__device__ __forceinline__ void ldsm4(u32* r, u32 a){
    asm volatile("ldmatrix.sync.aligned.m8n8.x4.shared.b16 {%0,%1,%2,%3},[%4];"
                 :"=r"(r[0]),"=r"(r[1]),"=r"(r[2]),"=r"(r[3]):"r"(a));
}
__device__ __forceinline__ void ldsm4t(u32* r, u32 a){
    asm volatile("ldmatrix.sync.aligned.m8n8.x4.trans.shared.b16 {%0,%1,%2,%3},[%4];"
                 :"=r"(r[0]),"=r"(r[1]),"=r"(r[2]),"=r"(r[3]):"r"(a));
}
__device__ __forceinline__ void mma4(float* c, const u32* a, const u32* b){
    asm volatile("mma.sync.aligned.m16n8k16.row.col.f32.bf16.bf16.f32 "
                 "{%0,%1,%2,%3},{%4,%5,%6,%7},{%8,%9},{%0,%1,%2,%3};"
                 :"+f"(c[0]),"+f"(c[1]),"+f"(c[2]),"+f"(c[3])
                 :"r"(a[0]),"r"(a[1]),"r"(a[2]),"r"(a[3]),"r"(b[0]),"r"(b[1]));
}
__device__ __forceinline__ float ex2f(float x){
    float y; asm("ex2.approx.ftz.f32 %0,%1;":"=f"(y):"f"(x)); return y;
}
__device__ __forceinline__ void cpa(u32 d, const void* s){
    asm volatile("cp.async.cg.shared.global [%0],[%1],16;"::"r"(d),"l"(s));
}
#define CPC asm volatile("cp.async.commit_group;")
#define CPW asm volatile("cp.async.wait_group 0;")
__device__ __forceinline__ u32 bits(__nv_bfloat162 v){ return *reinterpret_cast<u32*>(&v); }
__device__ __forceinline__ void split2(float x, float y, u32& h, u32& l){
    __nv_bfloat162 hh = __floats2bfloat162_rn(x, y);
    float2 hf = __bfloat1622float2(hh);
    h = bits(hh);
    l = bits(__floats2bfloat162_rn(x - hf.x, y - hf.y));
}
__device__ __forceinline__ void split8(float4 a, float4 b, uint4& h, uint4& l){
    split2(a.x, a.y, h.x, l.x); split2(a.z, a.w, h.y, l.y);
    split2(b.x, b.y, h.z, l.z); split2(b.z, b.w, h.w, l.w);
}

// ---------------------------------------------------------------------------
// prepW: split combined [Wk;Wq;Wv] into bf16 hi/lo planes.
// ---------------------------------------------------------------------------
__global__ __launch_bounds__(256) void prepw_kernel(
    const float* __restrict__ Wk, const float* __restrict__ Wq,
    const float* __restrict__ Wv)
{
    long wi = (long)blockIdx.x * 256 + threadIdx.x;
    if (wi < 192 * NC / 8) {
        int r = (int)(wi >> 7), c8 = (int)(wi & 127);
        const float* Wp = (r < 64)  ? Wk + (long)r * NC
                        : (r < 128) ? Wq + (long)(r - 64) * NC
                                    : Wv + (long)(r - 128) * NC;
        uint4 h, l;
        split8(*(const float4*)(Wp + c8 * 8), *(const float4*)(Wp + c8 * 8 + 4), h, l);
        ((uint4*)g_wh)[wi] = h; ((uint4*)g_wl)[wi] = l;
    }
}

// ---------------------------------------------------------------------------
// proj (round-13 proven M-split): out[16384,192] = x * [Wk;Wq;Wv]^T.
// grid 256 (M=64/block), block 256 (8 warps: wm=wid&1, wn=wid>>1; 32x48 tile).
// A single-buffered (x via LDG->split->STS); B double-buffered cp.async.
// smem 112KB -> 2 blocks/SM. Epilogue -> split q/k/v planes (q pre-scaled).
// ---------------------------------------------------------------------------
#define PA(p)   ((p)*8192)
#define PB(b,p) (16384 + (b)*49152 + (p)*24576)
#define PSM 114688

__global__ __launch_bounds__(256) void proj_kernel(const float* __restrict__ x)
{
    extern __shared__ char sm[];
    const u32 sb = s2u(sm);
    const int tid = threadIdx.x, lane = tid & 31, wid = tid >> 5;
    const int g = lane >> 2, t = lane & 3;
    const int l7 = lane & 7, b3 = (lane >> 3) & 1, h16 = lane >> 4;
    const int wm = wid & 1, wn = wid >> 1;
    const long tile = (long)blockIdx.x * 64;

    float4 ra[4];
    auto ldgA = [&](int c) {
#pragma unroll
        for (int it = 0; it < 2; it++) {
            int idx = tid + 256 * it, r = idx >> 3, gr = idx & 7;
            const float4* p = (const float4*)(x + (tile + r) * NC + c * 64 + gr * 8);
            ra[2*it]     = __ldcs(p);
            ra[2*it + 1] = __ldcs(p + 1);
        }
    };
    auto stsA = [&]() {
#pragma unroll
        for (int it = 0; it < 2; it++) {
            int idx = tid + 256 * it, r = idx >> 3, gr = idx & 7;
            uint4 h, l; split8(ra[2*it], ra[2*it + 1], h, l);
            u32 off = (u32)(r*128 + ((gr^(r&7))<<4));
            *(uint4*)(sm + PA(0) + off) = h;
            *(uint4*)(sm + PA(1) + off) = l;
        }
    };
    auto cpB = [&](int c, int buf) {
        const uint4* ws[2] = {(const uint4*)g_wh, (const uint4*)g_wl};
#pragma unroll
        for (int pl = 0; pl < 2; pl++)
#pragma unroll
            for (int it = 0; it < 6; it++) {
                int idx = tid + 256 * it, r = idx >> 3, gr = idx & 7;
                cpa(sb + PB(buf,pl) + r*128 + ((gr^(r&7))<<4),
                    ws[pl] + (long)r*128 + c*8 + gr);
            }
    };

    float acc[2][6][4];
#pragma unroll
    for (int i = 0; i < 2; i++)
#pragma unroll
        for (int j = 0; j < 6; j++)
#pragma unroll
            for (int e = 0; e < 4; e++) acc[i][j][e] = 0.f;

    ldgA(0); cpB(0, 0); CPC; stsA(); CPW; __syncthreads();

    for (int c = 0; c < 16; c++) {
        if (c < 15) { ldgA(c + 1); cpB(c + 1, (c + 1) & 1); CPC; }
        const u32 Ah = sb + PA(0), Al = sb + PA(1);
        const u32 Bh = sb + PB(c&1,0), Bl = sb + PB(c&1,1);
#pragma unroll
        for (int ks = 0; ks < 4; ks++) {
            u32 ah[2][4], al[2][4];
#pragma unroll
            for (int i = 0; i < 2; i++) {
                u32 off = (u32)((32*wm + 16*i + b3*8 + l7)*128 + (((2*ks + h16) ^ l7) << 4));
                ldsm4(ah[i], Ah + off); ldsm4(al[i], Al + off);
            }
#pragma unroll
            for (int jp = 0; jp < 3; jp++) {
                u32 off = (u32)((48*wn + (2*jp + h16)*8 + l7)*128 + (((2*ks + b3) ^ l7) << 4));
                u32 bh[4], bl[4];
                ldsm4(bh, Bh + off); ldsm4(bl, Bl + off);
#pragma unroll
                for (int i = 0; i < 2; i++) {
                    mma4(acc[i][2*jp],   ah[i], bh);   mma4(acc[i][2*jp],   ah[i], bl);
                    mma4(acc[i][2*jp],   al[i], bh);
                    mma4(acc[i][2*jp+1], ah[i], bh+2); mma4(acc[i][2*jp+1], ah[i], bl+2);
                    mma4(acc[i][2*jp+1], al[i], bh+2);
                }
            }
        }
        __syncthreads();
        if (c < 15) stsA();
        CPW;
        __syncthreads();
    }

#pragma unroll
    for (int i = 0; i < 2; i++)
#pragma unroll
        for (int j = 0; j < 6; j++) {
            int colg = 48*wn + 8*j + 2*t;
            int tn = colg >> 6, col = colg & 63;
            float sc = (tn == 1) ? SCALE_Q : 1.f;
            u32* hp = (tn == 0) ? g_kh : (tn == 1) ? g_qh : g_vh;
            u32* lp = (tn == 0) ? g_kl : (tn == 1) ? g_ql : g_vl;
            long r0 = tile + 32*wm + 16*i + g;
            u32 h, l;
            split2(acc[i][j][0]*sc, acc[i][j][1]*sc, h, l);
            hp[(r0*64 + col) >> 1] = h; lp[(r0*64 + col) >> 1] = l;
            split2(acc[i][j][2]*sc, acc[i][j][3]*sc, h, l);
            hp[((r0+8)*64 + col) >> 1] = h; lp[((r0+8)*64 + col) >> 1] = l;
        }
}

// ---------------------------------------------------------------------------
// attn (split-KV, fixed-point softmax m=0) — round-14 body, now with
// __launch_bounds__(256, 2) to co-schedule 2 blocks/SM (isolated A/B of the
// round-10 confound; latency hiding across CPW/barrier boundaries).
// grid (16 qt, 8 b, 2 z). z=0 -> kv [0..qt], z=1 -> [qt+1..2qt+1].
// ---------------------------------------------------------------------------
#define AQ(p)   ((p)*16384)
#define AK(b,p) (32768 + (b)*16384 + (p)*8192)
#define AV(b,p) (65536 + (b)*16384 + (p)*8192)
#define ASM 98304

__global__ __launch_bounds__(256, 2) void attn_kernel()
{
    extern __shared__ char sm[];
    const u32 sb = s2u(sm);
    const int tid = threadIdx.x, lane = tid & 31, w = tid >> 5;
    const int g = lane >> 2, t = lane & 3;
    const int l7 = lane & 7, b3 = (lane >> 3) & 1, h16 = lane >> 4;
    const int qt = blockIdx.x, b = blockIdx.y, z = blockIdx.z;
    const int kt0 = z ? (qt + 1) : 0;
    const int kt1 = z ? (2*qt + 1) : qt;
    const long qrow0 = (long)b*NT + qt*128;

    auto cpkv = [&](int kt, int buf) {
        long rb = (long)b*NT + kt*64;
        const uint4* srcs[4] = {(const uint4*)g_kh, (const uint4*)g_kl,
                                (const uint4*)g_vh, (const uint4*)g_vl};
        u32 dsts[4] = {sb+AK(buf,0), sb+AK(buf,1), sb+AV(buf,0), sb+AV(buf,1)};
#pragma unroll
        for (int p = 0; p < 4; p++)
#pragma unroll
            for (int it = 0; it < 2; it++) {
                int idx = tid + 256*it, r = idx >> 3, gr = idx & 7;
                cpa(dsts[p] + r*128 + ((gr^(r&7))<<4), srcs[p] + (rb + r)*8 + gr);
            }
    };

    {   // Q planes + first K/V
        const uint4* qs[2] = {(const uint4*)g_qh, (const uint4*)g_ql};
#pragma unroll
        for (int p = 0; p < 2; p++)
#pragma unroll
            for (int it = 0; it < 4; it++) {
                int idx = tid + 256*it, r = idx >> 3, gr = idx & 7;
                cpa(sb + AQ(p) + r*128 + ((gr^(r&7))<<4), qs[p] + (qrow0 + r)*8 + gr);
            }
        cpkv(kt0, 0); CPC; CPW; __syncthreads();
    }

    u32 qh[4][4], ql[4][4];
#pragma unroll
    for (int ks = 0; ks < 4; ks++) {
        u32 off = (u32)((16*w + b3*8 + l7)*128 + (((2*ks + h16) ^ l7) << 4));
        ldsm4(qh[ks], sb + AQ(0) + off);
        ldsm4(ql[ks], sb + AQ(1) + off);
    }

    float O[8][4];
#pragma unroll
    for (int j = 0; j < 8; j++)
#pragma unroll
        for (int e = 0; e < 4; e++) O[j][e] = 0.f;
    float L0 = 0.f, L1 = 0.f;
    const int rfirst = qt*128 + 16*w;

    for (int kt = kt0; kt <= kt1; kt++) {
        int buf = (kt - kt0) & 1;
        if (kt < kt1) { cpkv(kt + 1, buf ^ 1); CPC; }

        if (kt*64 <= rfirst + 15) {
            const u32 KH = sb+AK(buf,0), KL = sb+AK(buf,1);
            const u32 VH = sb+AV(buf,0), VL = sb+AV(buf,1);
            float s[8][4];
#pragma unroll
            for (int j = 0; j < 8; j++)
#pragma unroll
                for (int e = 0; e < 4; e++) s[j][e] = 0.f;

#pragma unroll
            for (int ks = 0; ks < 4; ks++)
#pragma unroll
                for (int jp = 0; jp < 4; jp++) {
                    u32 off = (u32)(((2*jp + h16)*8 + l7)*128 + (((2*ks + b3) ^ l7) << 4));
                    u32 bh[4], bl[4];
                    ldsm4(bh, KH + off); ldsm4(bl, KL + off);
                    mma4(s[2*jp],   qh[ks], bh);   mma4(s[2*jp],   qh[ks], bl);
                    mma4(s[2*jp],   ql[ks], bh);
                    mma4(s[2*jp+1], qh[ks], bh+2); mma4(s[2*jp+1], qh[ks], bl+2);
                    mma4(s[2*jp+1], ql[ks], bh+2);
                }

            if (kt*64 + 63 > rfirst) {
                int r0g = rfirst + g, r1g = r0g + 8;
#pragma unroll
                for (int j = 0; j < 8; j++) {
                    int cg = kt*64 + j*8 + 2*t;
                    if (cg > r0g)     s[j][0] = -1e30f;
                    if (cg + 1 > r0g) s[j][1] = -1e30f;
                    if (cg > r1g)     s[j][2] = -1e30f;
                    if (cg + 1 > r1g) s[j][3] = -1e30f;
                }
            }

            // fixed-point softmax: p = 2^s directly (bounded), no max/rescale
            float s0 = 0.f, s1 = 0.f;
#pragma unroll
            for (int j = 0; j < 8; j++) {
                s[j][0] = ex2f(s[j][0]); s[j][1] = ex2f(s[j][1]);
                s[j][2] = ex2f(s[j][2]); s[j][3] = ex2f(s[j][3]);
                s0 += s[j][0] + s[j][1];
                s1 += s[j][2] + s[j][3];
            }
            s0 += __shfl_xor_sync(~0u, s0, 1); s0 += __shfl_xor_sync(~0u, s0, 2);
            s1 += __shfl_xor_sync(~0u, s1, 1); s1 += __shfl_xor_sync(~0u, s1, 2);
            L0 += s0; L1 += s1;

            u32 ph[4][4], pl2[4][4];
#pragma unroll
            for (int ks = 0; ks < 4; ks++) {
                split2(s[2*ks][0],   s[2*ks][1],   ph[ks][0], pl2[ks][0]);
                split2(s[2*ks][2],   s[2*ks][3],   ph[ks][1], pl2[ks][1]);
                split2(s[2*ks+1][0], s[2*ks+1][1], ph[ks][2], pl2[ks][2]);
                split2(s[2*ks+1][2], s[2*ks+1][3], ph[ks][3], pl2[ks][3]);
            }

#pragma unroll
            for (int ks = 0; ks < 4; ks++)
#pragma unroll
                for (int jp = 0; jp < 4; jp++) {
                    u32 off = (u32)((16*ks + b3*8 + l7)*128 + (((2*jp + h16) ^ l7) << 4));
                    u32 vh[4], vl[4];
                    ldsm4t(vh, VH + off); ldsm4t(vl, VL + off);
                    mma4(O[2*jp],   ph[ks],  vh);   mma4(O[2*jp],   ph[ks],  vl);
                    mma4(O[2*jp],   pl2[ks], vh);
                    mma4(O[2*jp+1], ph[ks],  vh+2); mma4(O[2*jp+1], ph[ks],  vl+2);
                    mma4(O[2*jp+1], pl2[ks], vh+2);
                }
        }
        CPW; __syncthreads();
    }

    // write partials (unnormalized O + l)
    float* Od = z ? g_O1 : g_O0;
#pragma unroll
    for (int j = 0; j < 8; j++) {
        int col = j*8 + 2*t;
        *(float2*)(Od + (qrow0 + 16*w + g)*64 + col)     = make_float2(O[j][0], O[j][1]);
        *(float2*)(Od + (qrow0 + 16*w + g + 8)*64 + col) = make_float2(O[j][2], O[j][3]);
    }
    if (t == 0) {
        float* lp = z ? g_l1 : g_l0;
        lp[qrow0 + 16*w + g]     = L0;
        lp[qrow0 + 16*w + g + 8] = L1;
    }
}

// ---------------------------------------------------------------------------
// combine: out = (O0 + O1) / (l0 + l1). Block per 16 rows; scales via smem.
// ---------------------------------------------------------------------------
__global__ __launch_bounds__(256) void combine_kernel(float* __restrict__ out)
{
    __shared__ float cI[16];
    const long row0 = (long)blockIdx.x * 16;
    const int tid = threadIdx.x;
    if (tid < 16) {
        long r = row0 + tid;
        cI[tid] = 1.f / (g_l0[r] + g_l1[r]);
    }
    __syncthreads();
    long base = row0 * 16 + tid;
    float4 a = ((const float4*)g_O0)[base];
    float4 c = ((const float4*)g_O1)[base];
    float inv = cI[tid >> 4];
    float4 o;
    o.x = (a.x + c.x) * inv;
    o.y = (a.y + c.y) * inv;
    o.z = (a.z + c.z) * inv;
    o.w = (a.w + c.w) * inv;
    ((float4*)out)[base] = o;
}

extern "C" void kernel_launch(void* const* d_in, const int* in_sizes, int n_in,
                              void* d_out, int out_size)
{
    const float* x  = (const float*)d_in[0];
    const float* Wk = (const float*)d_in[1];
    const float* Wq = (const float*)d_in[2];
    const float* Wv = (const float*)d_in[3];
    float* out = (float*)d_out;

    prepw_kernel<<<96, 256>>>(Wk, Wq, Wv);

    cudaFuncSetAttribute(proj_kernel,
                         cudaFuncAttributeMaxDynamicSharedMemorySize, PSM);
    proj_kernel<<<256, 256, PSM>>>(x);

    cudaFuncSetAttribute(attn_kernel,
                         cudaFuncAttributeMaxDynamicSharedMemorySize, ASM);
    attn_kernel<<<dim3(16, 8, 2), 256, ASM>>>();

    combine_kernel<<<NR / 16, 256>>>(out);
}

// round 16
// speedup vs baseline: 1.0924x; 1.0924x over previous
#include <cuda_runtime.h>
#include <cuda_bf16.h>
#include <cstdint>

#define NB 8
#define NT 2048
#define NC 1024
#define NH 64
#define NR (NB*NT)
#define SCALE_Q 0.18033688011112042f  // 0.125 * log2(e)

typedef uint32_t u32;

// bf16 hi/lo split planes + split-KV scratch (device globals: allocation-free)
__device__ u32 g_wh[192*NC/2], g_wl[192*NC/2];
__device__ u32 g_qh[NR*NH/2], g_ql[NR*NH/2];
__device__ u32 g_kh[NR*NH/2], g_kl[NR*NH/2];
__device__ u32 g_vh[NR*NH/2], g_vl[NR*NH/2];
__device__ float g_O0[NR*NH], g_O1[NR*NH];
__device__ float g_l0[NR], g_l1[NR];

// ---------------- helpers ----------------
__device__ __forceinline__ u32 s2u(const void* p){
    u32 a; asm("{ .reg .u64 t; cvta.to.shared.u64 t, %1; cvt.u32.u64 %0, t; }":"=r"(a):"l"(p)); return a;
}
__device__ __forceinline__ void ldsm4(u32* r, u32 a){
    asm volatile("ldmatrix.sync.aligned.m8n8.x4.shared.b16 {%0,%1,%2,%3},[%4];"
                 :"=r"(r[0]),"=r"(r[1]),"=r"(r[2]),"=r"(r[3]):"r"(a));
}
__device__ __forceinline__ void ldsm4t(u32* r, u32 a){
    asm volatile("ldmatrix.sync.aligned.m8n8.x4.trans.shared.b16 {%0,%1,%2,%3},[%4];"
                 :"=r"(r[0]),"=r"(r[1]),"=r"(r[2]),"=r"(r[3]):"r"(a));
}
__device__ __forceinline__ void mma4(float* c, const u32* a, const u32* b){
    asm volatile("mma.sync.aligned.m16n8k16.row.col.f32.bf16.bf16.f32 "
                 "{%0,%1,%2,%3},{%4,%5,%6,%7},{%8,%9},{%0,%1,%2,%3};"
                 :"+f"(c[0]),"+f"(c[1]),"+f"(c[2]),"+f"(c[3])
                 :"r"(a[0]),"r"(a[1]),"r"(a[2]),"r"(a[3]),"r"(b[0]),"r"(b[1]));
}
__device__ __forceinline__ float ex2f(float x){
    float y; asm("ex2.approx.ftz.f32 %0,%1;":"=f"(y):"f"(x)); return y;
}
__device__ __forceinline__ void cpa(u32 d, const void* s){
    asm volatile("cp.async.cg.shared.global [%0],[%1],16;"::"r"(d),"l"(s));
}
#define CPC asm volatile("cp.async.commit_group;")
#define CPW asm volatile("cp.async.wait_group 0;")
__device__ __forceinline__ u32 bits(__nv_bfloat162 v){ return *reinterpret_cast<u32*>(&v); }
__device__ __forceinline__ void split2(float x, float y, u32& h, u32& l){
    __nv_bfloat162 hh = __floats2bfloat162_rn(x, y);
    float2 hf = __bfloat1622float2(hh);
    h = bits(hh);
    l = bits(__floats2bfloat162_rn(x - hf.x, y - hf.y));
}
__device__ __forceinline__ void split8(float4 a, float4 b, uint4& h, uint4& l){
    split2(a.x, a.y, h.x, l.x); split2(a.z, a.w, h.y, l.y);
    split2(b.x, b.y, h.z, l.z); split2(b.z, b.w, h.w, l.w);
}

// ---------------------------------------------------------------------------
// prepW: split combined [Wk;Wq;Wv] into bf16 hi/lo planes.
// ---------------------------------------------------------------------------
__global__ __launch_bounds__(256) void prepw_kernel(
    const float* __restrict__ Wk, const float* __restrict__ Wq,
    const float* __restrict__ Wv)
{
    long wi = (long)blockIdx.x * 256 + threadIdx.x;
    if (wi < 192 * NC / 8) {
        int r = (int)(wi >> 7), c8 = (int)(wi & 127);
        const float* Wp = (r < 64)  ? Wk + (long)r * NC
                        : (r < 128) ? Wq + (long)(r - 64) * NC
                                    : Wv + (long)(r - 128) * NC;
        uint4 h, l;
        split8(*(const float4*)(Wp + c8 * 8), *(const float4*)(Wp + c8 * 8 + 4), h, l);
        ((uint4*)g_wh)[wi] = h; ((uint4*)g_wl)[wi] = l;
    }
}

// ---------------------------------------------------------------------------
// proj (round-13 proven M-split): out[16384,192] = x * [Wk;Wq;Wv]^T.
// grid 256 (M=64/block), block 256 (8 warps: wm=wid&1, wn=wid>>1; 32x48 tile).
// A single-buffered (x via LDG->split->STS); B double-buffered cp.async.
// smem 112KB -> 2 blocks/SM. Epilogue -> split q/k/v planes (q pre-scaled).
// ---------------------------------------------------------------------------
#define PA(p)   ((p)*8192)
#define PB(b,p) (16384 + (b)*49152 + (p)*24576)
#define PSM 114688

__global__ __launch_bounds__(256) void proj_kernel(const float* __restrict__ x)
{
    extern __shared__ char sm[];
    const u32 sb = s2u(sm);
    const int tid = threadIdx.x, lane = tid & 31, wid = tid >> 5;
    const int g = lane >> 2, t = lane & 3;
    const int l7 = lane & 7, b3 = (lane >> 3) & 1, h16 = lane >> 4;
    const int wm = wid & 1, wn = wid >> 1;
    const long tile = (long)blockIdx.x * 64;

    float4 ra[4];
    auto ldgA = [&](int c) {
#pragma unroll
        for (int it = 0; it < 2; it++) {
            int idx = tid + 256 * it, r = idx >> 3, gr = idx & 7;
            const float4* p = (const float4*)(x + (tile + r) * NC + c * 64 + gr * 8);
            ra[2*it]     = __ldcs(p);
            ra[2*it + 1] = __ldcs(p + 1);
        }
    };
    auto stsA = [&]() {
#pragma unroll
        for (int it = 0; it < 2; it++) {
            int idx = tid + 256 * it, r = idx >> 3, gr = idx & 7;
            uint4 h, l; split8(ra[2*it], ra[2*it + 1], h, l);
            u32 off = (u32)(r*128 + ((gr^(r&7))<<4));
            *(uint4*)(sm + PA(0) + off) = h;
            *(uint4*)(sm + PA(1) + off) = l;
        }
    };
    auto cpB = [&](int c, int buf) {
        const uint4* ws[2] = {(const uint4*)g_wh, (const uint4*)g_wl};
#pragma unroll
        for (int pl = 0; pl < 2; pl++)
#pragma unroll
            for (int it = 0; it < 6; it++) {
                int idx = tid + 256 * it, r = idx >> 3, gr = idx & 7;
                cpa(sb + PB(buf,pl) + r*128 + ((gr^(r&7))<<4),
                    ws[pl] + (long)r*128 + c*8 + gr);
            }
    };

    float acc[2][6][4];
#pragma unroll
    for (int i = 0; i < 2; i++)
#pragma unroll
        for (int j = 0; j < 6; j++)
#pragma unroll
            for (int e = 0; e < 4; e++) acc[i][j][e] = 0.f;

    ldgA(0); cpB(0, 0); CPC; stsA(); CPW; __syncthreads();

    for (int c = 0; c < 16; c++) {
        if (c < 15) { ldgA(c + 1); cpB(c + 1, (c + 1) & 1); CPC; }
        const u32 Ah = sb + PA(0), Al = sb + PA(1);
        const u32 Bh = sb + PB(c&1,0), Bl = sb + PB(c&1,1);
#pragma unroll
        for (int ks = 0; ks < 4; ks++) {
            u32 ah[2][4], al[2][4];
#pragma unroll
            for (int i = 0; i < 2; i++) {
                u32 off = (u32)((32*wm + 16*i + b3*8 + l7)*128 + (((2*ks + h16) ^ l7) << 4));
                ldsm4(ah[i], Ah + off); ldsm4(al[i], Al + off);
            }
#pragma unroll
            for (int jp = 0; jp < 3; jp++) {
                u32 off = (u32)((48*wn + (2*jp + h16)*8 + l7)*128 + (((2*ks + b3) ^ l7) << 4));
                u32 bh[4], bl[4];
                ldsm4(bh, Bh + off); ldsm4(bl, Bl + off);
#pragma unroll
                for (int i = 0; i < 2; i++) {
                    mma4(acc[i][2*jp],   ah[i], bh);   mma4(acc[i][2*jp],   ah[i], bl);
                    mma4(acc[i][2*jp],   al[i], bh);
                    mma4(acc[i][2*jp+1], ah[i], bh+2); mma4(acc[i][2*jp+1], ah[i], bl+2);
                    mma4(acc[i][2*jp+1], al[i], bh+2);
                }
            }
        }
        __syncthreads();
        if (c < 15) stsA();
        CPW;
        __syncthreads();
    }

#pragma unroll
    for (int i = 0; i < 2; i++)
#pragma unroll
        for (int j = 0; j < 6; j++) {
            int colg = 48*wn + 8*j + 2*t;
            int tn = colg >> 6, col = colg & 63;
            float sc = (tn == 1) ? SCALE_Q : 1.f;
            u32* hp = (tn == 0) ? g_kh : (tn == 1) ? g_qh : g_vh;
            u32* lp = (tn == 0) ? g_kl : (tn == 1) ? g_ql : g_vl;
            long r0 = tile + 32*wm + 16*i + g;
            u32 h, l;
            split2(acc[i][j][0]*sc, acc[i][j][1]*sc, h, l);
            hp[(r0*64 + col) >> 1] = h; lp[(r0*64 + col) >> 1] = l;
            split2(acc[i][j][2]*sc, acc[i][j][3]*sc, h, l);
            hp[((r0+8)*64 + col) >> 1] = h; lp[((r0+8)*64 + col) >> 1] = l;
        }
}

// ---------------------------------------------------------------------------
// attn (split-KV, fixed-point softmax m=0, Tk=128): each step loads a PAIR of
// 64-row K/V tiles (64KB) and computes both halves with ONE CPW+barrier —
// barrier/pipeline overhead halves vs Tk=64. 1 block/SM (co-residency proven
// harmful in R15). grid (16 qt, 8 b, 2 z). z=0 -> kv [0..qt],
// z=1 -> [qt+1..2qt+1]. Phantom trailing half: load clamped (tile<=31, never
// OOB), compute guarded by kt<=kt1 (no double count across z).
// ---------------------------------------------------------------------------
#define AQ(p)   ((p)*16384)                       // Q: 128 rows x 2 planes = 32KB
#define AK(b,p) (32768 + (b)*32768 + (p)*16384)   // K: 128 rows, 2 buf x 2 pl = 64KB
#define AV(b,p) (98304 + (b)*32768 + (p)*16384)   // V: same = 64KB
#define ASM 163840

__global__ __launch_bounds__(256) void attn_kernel()
{
    extern __shared__ char sm[];
    const u32 sb = s2u(sm);
    const int tid = threadIdx.x, lane = tid & 31, w = tid >> 5;
    const int g = lane >> 2, t = lane & 3;
    const int l7 = lane & 7, b3 = (lane >> 3) & 1, h16 = lane >> 4;
    const int qt = blockIdx.x, b = blockIdx.y, z = blockIdx.z;
    const int kt0 = z ? (qt + 1) : 0;
    const int kt1 = z ? (2*qt + 1) : qt;
    const long qrow0 = (long)b*NT + qt*128;

    // load a PAIR of 64-row k-tiles (s, s+1) into buf; clamp tile index to 31
    auto cpkv = [&](int s, int buf) {
#pragma unroll
        for (int h = 0; h < 2; h++) {
            int tile2 = s + h; if (tile2 > 31) tile2 = 31;
            long rb = (long)b*NT + tile2*64;
            const uint4* srcs[4] = {(const uint4*)g_kh, (const uint4*)g_kl,
                                    (const uint4*)g_vh, (const uint4*)g_vl};
            u32 dsts[4] = {sb+AK(buf,0), sb+AK(buf,1), sb+AV(buf,0), sb+AV(buf,1)};
#pragma unroll
            for (int p = 0; p < 4; p++)
#pragma unroll
                for (int it = 0; it < 2; it++) {
                    int idx = tid + 256*it, r = idx >> 3, gr = idx & 7;
                    cpa(dsts[p] + (h*64 + r)*128 + ((gr^(r&7))<<4),
                        srcs[p] + (rb + r)*8 + gr);
                }
        }
    };

    {   // Q planes + first K/V pair
        const uint4* qs[2] = {(const uint4*)g_qh, (const uint4*)g_ql};
#pragma unroll
        for (int p = 0; p < 2; p++)
#pragma unroll
            for (int it = 0; it < 4; it++) {
                int idx = tid + 256*it, r = idx >> 3, gr = idx & 7;
                cpa(sb + AQ(p) + r*128 + ((gr^(r&7))<<4), qs[p] + (qrow0 + r)*8 + gr);
            }
        cpkv(kt0, 0); CPC; CPW; __syncthreads();
    }

    u32 qh[4][4], ql[4][4];
#pragma unroll
    for (int ks = 0; ks < 4; ks++) {
        u32 off = (u32)((16*w + b3*8 + l7)*128 + (((2*ks + h16) ^ l7) << 4));
        ldsm4(qh[ks], sb + AQ(0) + off);
        ldsm4(ql[ks], sb + AQ(1) + off);
    }

    float O[8][4];
#pragma unroll
    for (int j = 0; j < 8; j++)
#pragma unroll
        for (int e = 0; e < 4; e++) O[j][e] = 0.f;
    float L0 = 0.f, L1 = 0.f;
    const int rfirst = qt*128 + 16*w;
    const int npairs = (kt1 - kt0 + 2) >> 1;

    for (int i = 0; i < npairs; i++) {
        const int s = kt0 + 2*i;
        const int buf = i & 1;
        if (i + 1 < npairs) { cpkv(kt0 + 2*(i+1), buf ^ 1); CPC; }

#pragma unroll
        for (int h = 0; h < 2; h++) {
            const int kt = s + h;
            if (kt <= kt1 && kt*64 <= rfirst + 15) {
                const u32 KH = sb+AK(buf,0) + h*8192, KL = sb+AK(buf,1) + h*8192;
                const u32 VH = sb+AV(buf,0) + h*8192, VL = sb+AV(buf,1) + h*8192;
                float s4[8][4];
#pragma unroll
                for (int j = 0; j < 8; j++)
#pragma unroll
                    for (int e = 0; e < 4; e++) s4[j][e] = 0.f;

#pragma unroll
                for (int ks = 0; ks < 4; ks++)
#pragma unroll
                    for (int jp = 0; jp < 4; jp++) {
                        u32 off = (u32)(((2*jp + h16)*8 + l7)*128 + (((2*ks + b3) ^ l7) << 4));
                        u32 bh[4], bl[4];
                        ldsm4(bh, KH + off); ldsm4(bl, KL + off);
                        mma4(s4[2*jp],   qh[ks], bh);   mma4(s4[2*jp],   qh[ks], bl);
                        mma4(s4[2*jp],   ql[ks], bh);
                        mma4(s4[2*jp+1], qh[ks], bh+2); mma4(s4[2*jp+1], qh[ks], bl+2);
                        mma4(s4[2*jp+1], ql[ks], bh+2);
                    }

                if (kt*64 + 63 > rfirst) {
                    int r0g = rfirst + g, r1g = r0g + 8;
#pragma unroll
                    for (int j = 0; j < 8; j++) {
                        int cg = kt*64 + j*8 + 2*t;
                        if (cg > r0g)     s4[j][0] = -1e30f;
                        if (cg + 1 > r0g) s4[j][1] = -1e30f;
                        if (cg > r1g)     s4[j][2] = -1e30f;
                        if (cg + 1 > r1g) s4[j][3] = -1e30f;
                    }
                }

                // fixed-point softmax: p = 2^s directly (bounded)
                float s0 = 0.f, s1 = 0.f;
#pragma unroll
                for (int j = 0; j < 8; j++) {
                    s4[j][0] = ex2f(s4[j][0]); s4[j][1] = ex2f(s4[j][1]);
                    s4[j][2] = ex2f(s4[j][2]); s4[j][3] = ex2f(s4[j][3]);
                    s0 += s4[j][0] + s4[j][1];
                    s1 += s4[j][2] + s4[j][3];
                }
                s0 += __shfl_xor_sync(~0u, s0, 1); s0 += __shfl_xor_sync(~0u, s0, 2);
                s1 += __shfl_xor_sync(~0u, s1, 1); s1 += __shfl_xor_sync(~0u, s1, 2);
                L0 += s0; L1 += s1;

                u32 ph[4][4], pl2[4][4];
#pragma unroll
                for (int ks = 0; ks < 4; ks++) {
                    split2(s4[2*ks][0],   s4[2*ks][1],   ph[ks][0], pl2[ks][0]);
                    split2(s4[2*ks][2],   s4[2*ks][3],   ph[ks][1], pl2[ks][1]);
                    split2(s4[2*ks+1][0], s4[2*ks+1][1], ph[ks][2], pl2[ks][2]);
                    split2(s4[2*ks+1][2], s4[2*ks+1][3], ph[ks][3], pl2[ks][3]);
                }

#pragma unroll
                for (int ks = 0; ks < 4; ks++)
#pragma unroll
                    for (int jp = 0; jp < 4; jp++) {
                        u32 off = (u32)((16*ks + b3*8 + l7)*128 + (((2*jp + h16) ^ l7) << 4));
                        u32 vh[4], vl[4];
                        ldsm4t(vh, VH + off); ldsm4t(vl, VL + off);
                        mma4(O[2*jp],   ph[ks],  vh);   mma4(O[2*jp],   ph[ks],  vl);
                        mma4(O[2*jp],   pl2[ks], vh);
                        mma4(O[2*jp+1], ph[ks],  vh+2); mma4(O[2*jp+1], ph[ks],  vl+2);
                        mma4(O[2*jp+1], pl2[ks], vh+2);
                    }
            }
        }
        CPW; __syncthreads();
    }

    // write partials (unnormalized O + l)
    float* Od = z ? g_O1 : g_O0;
#pragma unroll
    for (int j = 0; j < 8; j++) {
        int col = j*8 + 2*t;
        *(float2*)(Od + (qrow0 + 16*w + g)*64 + col)     = make_float2(O[j][0], O[j][1]);
        *(float2*)(Od + (qrow0 + 16*w + g + 8)*64 + col) = make_float2(O[j][2], O[j][3]);
    }
    if (t == 0) {
        float* lp = z ? g_l1 : g_l0;
        lp[qrow0 + 16*w + g]     = L0;
        lp[qrow0 + 16*w + g + 8] = L1;
    }
}

// ---------------------------------------------------------------------------
// combine: out = (O0 + O1) / (l0 + l1). Block per 16 rows; scales via smem.
// ---------------------------------------------------------------------------
__global__ __launch_bounds__(256) void combine_kernel(float* __restrict__ out)
{
    __shared__ float cI[16];
    const long row0 = (long)blockIdx.x * 16;
    const int tid = threadIdx.x;
    if (tid < 16) {
        long r = row0 + tid;
        cI[tid] = 1.f / (g_l0[r] + g_l1[r]);
    }
    __syncthreads();
    long base = row0 * 16 + tid;
    float4 a = ((const float4*)g_O0)[base];
    float4 c = ((const float4*)g_O1)[base];
    float inv = cI[tid >> 4];
    float4 o;
    o.x = (a.x + c.x) * inv;
    o.y = (a.y + c.y) * inv;
    o.z = (a.z + c.z) * inv;
    o.w = (a.w + c.w) * inv;
    ((float4*)out)[base] = o;
}

extern "C" void kernel_launch(void* const* d_in, const int* in_sizes, int n_in,
                              void* d_out, int out_size)
{
    const float* x  = (const float*)d_in[0];
    const float* Wk = (const float*)d_in[1];
    const float* Wq = (const float*)d_in[2];
    const float* Wv = (const float*)d_in[3];
    float* out = (float*)d_out;

    prepw_kernel<<<96, 256>>>(Wk, Wq, Wv);

    cudaFuncSetAttribute(proj_kernel,
                         cudaFuncAttributeMaxDynamicSharedMemorySize, PSM);
    proj_kernel<<<256, 256, PSM>>>(x);

    cudaFuncSetAttribute(attn_kernel,
                         cudaFuncAttributeMaxDynamicSharedMemorySize, ASM);
    attn_kernel<<<dim3(16, 8, 2), 256, ASM>>>();

    combine_kernel<<<NR / 16, 256>>>(out);
}

// round 17
// speedup vs baseline: 1.3052x; 1.1948x over previous
#include <cuda_runtime.h>
#include <cuda_bf16.h>
#include <cstdint>

#define NB 8
#define NT 2048
#define NC 1024
#define NH 64
#define NR (NB*NT)
#define SCALE_Q 0.18033688011112042f  // 0.125 * log2(e)

typedef uint32_t u32;

// bf16 hi/lo split planes + split-KV scratch (device globals: allocation-free)
__device__ u32 g_wh[192*NC/2], g_wl[192*NC/2];
__device__ u32 g_qh[NR*NH/2], g_ql[NR*NH/2];
__device__ u32 g_kh[NR*NH/2], g_kl[NR*NH/2];
__device__ u32 g_vh[NR*NH/2], g_vl[NR*NH/2];
__device__ float g_O0[NR*NH], g_O1[NR*NH];
__device__ float g_l0[NR], g_l1[NR];

// ---------------- helpers ----------------
__device__ __forceinline__ u32 s2u(const void* p){
    u32 a; asm("{ .reg .u64 t; cvta.to.shared.u64 t, %1; cvt.u32.u64 %0, t; }":"=r"(a):"l"(p)); return a;
}
__device__ __forceinline__ void ldsm4(u32* r, u32 a){
    asm volatile("ldmatrix.sync.aligned.m8n8.x4.shared.b16 {%0,%1,%2,%3},[%4];"
                 :"=r"(r[0]),"=r"(r[1]),"=r"(r[2]),"=r"(r[3]):"r"(a));
}
__device__ __forceinline__ void ldsm4t(u32* r, u32 a){
    asm volatile("ldmatrix.sync.aligned.m8n8.x4.trans.shared.b16 {%0,%1,%2,%3},[%4];"
                 :"=r"(r[0]),"=r"(r[1]),"=r"(r[2]),"=r"(r[3]):"r"(a));
}
__device__ __forceinline__ void mma4(float* c, const u32* a, const u32* b){
    asm volatile("mma.sync.aligned.m16n8k16.row.col.f32.bf16.bf16.f32 "
                 "{%0,%1,%2,%3},{%4,%5,%6,%7},{%8,%9},{%0,%1,%2,%3};"
                 :"+f"(c[0]),"+f"(c[1]),"+f"(c[2]),"+f"(c[3])
                 :"r"(a[0]),"r"(a[1]),"r"(a[2]),"r"(a[3]),"r"(b[0]),"r"(b[1]));
}
__device__ __forceinline__ float ex2f(float x){
    float y; asm("ex2.approx.ftz.f32 %0,%1;":"=f"(y):"f"(x)); return y;
}
__device__ __forceinline__ void cpa(u32 d, const void* s){
    asm volatile("cp.async.cg.shared.global [%0],[%1],16;"::"r"(d),"l"(s));
}
#define CPC asm volatile("cp.async.commit_group;")
#define CPW asm volatile("cp.async.wait_group 0;")
__device__ __forceinline__ u32 bits(__nv_bfloat162 v){ return *reinterpret_cast<u32*>(&v); }
__device__ __forceinline__ void split2(float x, float y, u32& h, u32& l){
    __nv_bfloat162 hh = __floats2bfloat162_rn(x, y);
    float2 hf = __bfloat1622float2(hh);
    h = bits(hh);
    l = bits(__floats2bfloat162_rn(x - hf.x, y - hf.y));
}
__device__ __forceinline__ void split8(float4 a, float4 b, uint4& h, uint4& l){
    split2(a.x, a.y, h.x, l.x); split2(a.z, a.w, h.y, l.y);
    split2(b.x, b.y, h.z, l.z); split2(b.z, b.w, h.w, l.w);
}

// ---------------------------------------------------------------------------
// prepW: split combined [Wk;Wq;Wv] into bf16 hi/lo planes.
// ---------------------------------------------------------------------------
__global__ __launch_bounds__(256) void prepw_kernel(
    const float* __restrict__ Wk, const float* __restrict__ Wq,
    const float* __restrict__ Wv)
{
    long wi = (long)blockIdx.x * 256 + threadIdx.x;
    if (wi < 192 * NC / 8) {
        int r = (int)(wi >> 7), c8 = (int)(wi & 127);
        const float* Wp = (r < 64)  ? Wk + (long)r * NC
                        : (r < 128) ? Wq + (long)(r - 64) * NC
                                    : Wv + (long)(r - 128) * NC;
        uint4 h, l;
        split8(*(const float4*)(Wp + c8 * 8), *(const float4*)(Wp + c8 * 8 + 4), h, l);
        ((uint4*)g_wh)[wi] = h; ((uint4*)g_wl)[wi] = l;
    }
}

// ---------------------------------------------------------------------------
// proj (round-13 proven M-split): out[16384,192] = x * [Wk;Wq;Wv]^T.
// grid 256 (M=64/block), block 256 (8 warps: wm=wid&1, wn=wid>>1; 32x48 tile).
// A single-buffered (x via LDG->split->STS); B double-buffered cp.async.
// smem 112KB -> 2 blocks/SM. Epilogue -> split q/k/v planes (q pre-scaled).
// ---------------------------------------------------------------------------
#define PA(p)   ((p)*8192)
#define PB(b,p) (16384 + (b)*49152 + (p)*24576)
#define PSM 114688

__global__ __launch_bounds__(256) void proj_kernel(const float* __restrict__ x)
{
    extern __shared__ char sm[];
    const u32 sb = s2u(sm);
    const int tid = threadIdx.x, lane = tid & 31, wid = tid >> 5;
    const int g = lane >> 2, t = lane & 3;
    const int l7 = lane & 7, b3 = (lane >> 3) & 1, h16 = lane >> 4;
    const int wm = wid & 1, wn = wid >> 1;
    const long tile = (long)blockIdx.x * 64;

    float4 ra[4];
    auto ldgA = [&](int c) {
#pragma unroll
        for (int it = 0; it < 2; it++) {
            int idx = tid + 256 * it, r = idx >> 3, gr = idx & 7;
            const float4* p = (const float4*)(x + (tile + r) * NC + c * 64 + gr * 8);
            ra[2*it]     = __ldcs(p);
            ra[2*it + 1] = __ldcs(p + 1);
        }
    };
    auto stsA = [&]() {
#pragma unroll
        for (int it = 0; it < 2; it++) {
            int idx = tid + 256 * it, r = idx >> 3, gr = idx & 7;
            uint4 h, l; split8(ra[2*it], ra[2*it + 1], h, l);
            u32 off = (u32)(r*128 + ((gr^(r&7))<<4));
            *(uint4*)(sm + PA(0) + off) = h;
            *(uint4*)(sm + PA(1) + off) = l;
        }
    };
    auto cpB = [&](int c, int buf) {
        const uint4* ws[2] = {(const uint4*)g_wh, (const uint4*)g_wl};
#pragma unroll
        for (int pl = 0; pl < 2; pl++)
#pragma unroll
            for (int it = 0; it < 6; it++) {
                int idx = tid + 256 * it, r = idx >> 3, gr = idx & 7;
                cpa(sb + PB(buf,pl) + r*128 + ((gr^(r&7))<<4),
                    ws[pl] + (long)r*128 + c*8 + gr);
            }
    };

    float acc[2][6][4];
#pragma unroll
    for (int i = 0; i < 2; i++)
#pragma unroll
        for (int j = 0; j < 6; j++)
#pragma unroll
            for (int e = 0; e < 4; e++) acc[i][j][e] = 0.f;

    ldgA(0); cpB(0, 0); CPC; stsA(); CPW; __syncthreads();

    for (int c = 0; c < 16; c++) {
        if (c < 15) { ldgA(c + 1); cpB(c + 1, (c + 1) & 1); CPC; }
        const u32 Ah = sb + PA(0), Al = sb + PA(1);
        const u32 Bh = sb + PB(c&1,0), Bl = sb + PB(c&1,1);
#pragma unroll
        for (int ks = 0; ks < 4; ks++) {
            u32 ah[2][4], al[2][4];
#pragma unroll
            for (int i = 0; i < 2; i++) {
                u32 off = (u32)((32*wm + 16*i + b3*8 + l7)*128 + (((2*ks + h16) ^ l7) << 4));
                ldsm4(ah[i], Ah + off); ldsm4(al[i], Al + off);
            }
#pragma unroll
            for (int jp = 0; jp < 3; jp++) {
                u32 off = (u32)((48*wn + (2*jp + h16)*8 + l7)*128 + (((2*ks + b3) ^ l7) << 4));
                u32 bh[4], bl[4];
                ldsm4(bh, Bh + off); ldsm4(bl, Bl + off);
#pragma unroll
                for (int i = 0; i < 2; i++) {
                    mma4(acc[i][2*jp],   ah[i], bh);   mma4(acc[i][2*jp],   ah[i], bl);
                    mma4(acc[i][2*jp],   al[i], bh);
                    mma4(acc[i][2*jp+1], ah[i], bh+2); mma4(acc[i][2*jp+1], ah[i], bl+2);
                    mma4(acc[i][2*jp+1], al[i], bh+2);
                }
            }
        }
        __syncthreads();
        if (c < 15) stsA();
        CPW;
        __syncthreads();
    }

#pragma unroll
    for (int i = 0; i < 2; i++)
#pragma unroll
        for (int j = 0; j < 6; j++) {
            int colg = 48*wn + 8*j + 2*t;
            int tn = colg >> 6, col = colg & 63;
            float sc = (tn == 1) ? SCALE_Q : 1.f;
            u32* hp = (tn == 0) ? g_kh : (tn == 1) ? g_qh : g_vh;
            u32* lp = (tn == 0) ? g_kl : (tn == 1) ? g_ql : g_vl;
            long r0 = tile + 32*wm + 16*i + g;
            u32 h, l;
            split2(acc[i][j][0]*sc, acc[i][j][1]*sc, h, l);
            hp[(r0*64 + col) >> 1] = h; lp[(r0*64 + col) >> 1] = l;
            split2(acc[i][j][2]*sc, acc[i][j][3]*sc, h, l);
            hp[((r0+8)*64 + col) >> 1] = h; lp[((r0+8)*64 + col) >> 1] = l;
        }
}

// ---------------------------------------------------------------------------
// attn (split-KV, fixed-point softmax m=0, Tk=128) — round-16 body, with a
// 1D grid sorted GLOBALLY longest-first: idx -> qt = 15-(idx>>4), so all
// 16-step blocks (both z!) start in wave 1 and short blocks fill the tail.
// 1 block/SM (co-residency proven harmful). Load clamped / compute guarded
// for the phantom trailing half.
// ---------------------------------------------------------------------------
#define AQ(p)   ((p)*16384)
#define AK(b,p) (32768 + (b)*32768 + (p)*16384)
#define AV(b,p) (98304 + (b)*32768 + (p)*16384)
#define ASM 163840

__global__ __launch_bounds__(256) void attn_kernel()
{
    extern __shared__ char sm[];
    const u32 sb = s2u(sm);
    const int tid = threadIdx.x, lane = tid & 31, w = tid >> 5;
    const int g = lane >> 2, t = lane & 3;
    const int l7 = lane & 7, b3 = (lane >> 3) & 1, h16 = lane >> 4;
    // globally sorted longest-first: 16 blocks per qt (8 b x 2 z), qt desc
    const int idx = blockIdx.x;
    const int qt = 15 - (idx >> 4);
    const int b = idx & 7;
    const int z = (idx >> 3) & 1;
    const int kt0 = z ? (qt + 1) : 0;
    const int kt1 = z ? (2*qt + 1) : qt;
    const long qrow0 = (long)b*NT + qt*128;

    auto cpkv = [&](int s, int buf) {
#pragma unroll
        for (int h = 0; h < 2; h++) {
            int tile2 = s + h; if (tile2 > 31) tile2 = 31;
            long rb = (long)b*NT + tile2*64;
            const uint4* srcs[4] = {(const uint4*)g_kh, (const uint4*)g_kl,
                                    (const uint4*)g_vh, (const uint4*)g_vl};
            u32 dsts[4] = {sb+AK(buf,0), sb+AK(buf,1), sb+AV(buf,0), sb+AV(buf,1)};
#pragma unroll
            for (int p = 0; p < 4; p++)
#pragma unroll
                for (int it = 0; it < 2; it++) {
                    int idx2 = tid + 256*it, r = idx2 >> 3, gr = idx2 & 7;
                    cpa(dsts[p] + (h*64 + r)*128 + ((gr^(r&7))<<4),
                        srcs[p] + (rb + r)*8 + gr);
                }
        }
    };

    {   // Q planes + first K/V pair
        const uint4* qs[2] = {(const uint4*)g_qh, (const uint4*)g_ql};
#pragma unroll
        for (int p = 0; p < 2; p++)
#pragma unroll
            for (int it = 0; it < 4; it++) {
                int idx2 = tid + 256*it, r = idx2 >> 3, gr = idx2 & 7;
                cpa(sb + AQ(p) + r*128 + ((gr^(r&7))<<4), qs[p] + (qrow0 + r)*8 + gr);
            }
        cpkv(kt0, 0); CPC; CPW; __syncthreads();
    }

    u32 qh[4][4], ql[4][4];
#pragma unroll
    for (int ks = 0; ks < 4; ks++) {
        u32 off = (u32)((16*w + b3*8 + l7)*128 + (((2*ks + h16) ^ l7) << 4));
        ldsm4(qh[ks], sb + AQ(0) + off);
        ldsm4(ql[ks], sb + AQ(1) + off);
    }

    float O[8][4];
#pragma unroll
    for (int j = 0; j < 8; j++)
#pragma unroll
        for (int e = 0; e < 4; e++) O[j][e] = 0.f;
    float L0 = 0.f, L1 = 0.f;
    const int rfirst = qt*128 + 16*w;
    const int npairs = (kt1 - kt0 + 2) >> 1;

    for (int i = 0; i < npairs; i++) {
        const int s = kt0 + 2*i;
        const int buf = i & 1;
        if (i + 1 < npairs) { cpkv(kt0 + 2*(i+1), buf ^ 1); CPC; }

#pragma unroll
        for (int h = 0; h < 2; h++) {
            const int kt = s + h;
            if (kt <= kt1 && kt*64 <= rfirst + 15) {
                const u32 KH = sb+AK(buf,0) + h*8192, KL = sb+AK(buf,1) + h*8192;
                const u32 VH = sb+AV(buf,0) + h*8192, VL = sb+AV(buf,1) + h*8192;
                float s4[8][4];
#pragma unroll
                for (int j = 0; j < 8; j++)
#pragma unroll
                    for (int e = 0; e < 4; e++) s4[j][e] = 0.f;

#pragma unroll
                for (int ks = 0; ks < 4; ks++)
#pragma unroll
                    for (int jp = 0; jp < 4; jp++) {
                        u32 off = (u32)(((2*jp + h16)*8 + l7)*128 + (((2*ks + b3) ^ l7) << 4));
                        u32 bh[4], bl[4];
                        ldsm4(bh, KH + off); ldsm4(bl, KL + off);
                        mma4(s4[2*jp],   qh[ks], bh);   mma4(s4[2*jp],   qh[ks], bl);
                        mma4(s4[2*jp],   ql[ks], bh);
                        mma4(s4[2*jp+1], qh[ks], bh+2); mma4(s4[2*jp+1], qh[ks], bl+2);
                        mma4(s4[2*jp+1], ql[ks], bh+2);
                    }

                if (kt*64 + 63 > rfirst) {
                    int r0g = rfirst + g, r1g = r0g + 8;
#pragma unroll
                    for (int j = 0; j < 8; j++) {
                        int cg = kt*64 + j*8 + 2*t;
                        if (cg > r0g)     s4[j][0] = -1e30f;
                        if (cg + 1 > r0g) s4[j][1] = -1e30f;
                        if (cg > r1g)     s4[j][2] = -1e30f;
                        if (cg + 1 > r1g) s4[j][3] = -1e30f;
                    }
                }

                float s0 = 0.f, s1 = 0.f;
#pragma unroll
                for (int j = 0; j < 8; j++) {
                    s4[j][0] = ex2f(s4[j][0]); s4[j][1] = ex2f(s4[j][1]);
                    s4[j][2] = ex2f(s4[j][2]); s4[j][3] = ex2f(s4[j][3]);
                    s0 += s4[j][0] + s4[j][1];
                    s1 += s4[j][2] + s4[j][3];
                }
                s0 += __shfl_xor_sync(~0u, s0, 1); s0 += __shfl_xor_sync(~0u, s0, 2);
                s1 += __shfl_xor_sync(~0u, s1, 1); s1 += __shfl_xor_sync(~0u, s1, 2);
                L0 += s0; L1 += s1;

                u32 ph[4][4], pl2[4][4];
#pragma unroll
                for (int ks = 0; ks < 4; ks++) {
                    split2(s4[2*ks][0],   s4[2*ks][1],   ph[ks][0], pl2[ks][0]);
                    split2(s4[2*ks][2],   s4[2*ks][3],   ph[ks][1], pl2[ks][1]);
                    split2(s4[2*ks+1][0], s4[2*ks+1][1], ph[ks][2], pl2[ks][2]);
                    split2(s4[2*ks+1][2], s4[2*ks+1][3], ph[ks][3], pl2[ks][3]);
                }

#pragma unroll
                for (int ks = 0; ks < 4; ks++)
#pragma unroll
                    for (int jp = 0; jp < 4; jp++) {
                        u32 off = (u32)((16*ks + b3*8 + l7)*128 + (((2*jp + h16) ^ l7) << 4));
                        u32 vh[4], vl[4];
                        ldsm4t(vh, VH + off); ldsm4t(vl, VL + off);
                        mma4(O[2*jp],   ph[ks],  vh);   mma4(O[2*jp],   ph[ks],  vl);
                        mma4(O[2*jp],   pl2[ks], vh);
                        mma4(O[2*jp+1], ph[ks],  vh+2); mma4(O[2*jp+1], ph[ks],  vl+2);
                        mma4(O[2*jp+1], pl2[ks], vh+2);
                    }
            }
        }
        CPW; __syncthreads();
    }

    // write partials (unnormalized O + l)
    float* Od = z ? g_O1 : g_O0;
#pragma unroll
    for (int j = 0; j < 8; j++) {
        int col = j*8 + 2*t;
        *(float2*)(Od + (qrow0 + 16*w + g)*64 + col)     = make_float2(O[j][0], O[j][1]);
        *(float2*)(Od + (qrow0 + 16*w + g + 8)*64 + col) = make_float2(O[j][2], O[j][3]);
    }
    if (t == 0) {
        float* lp = z ? g_l1 : g_l0;
        lp[qrow0 + 16*w + g]     = L0;
        lp[qrow0 + 16*w + g + 8] = L1;
    }
}

// ---------------------------------------------------------------------------
// combine: out = (O0 + O1) / (l0 + l1). Block per 16 rows; scales via smem.
// ---------------------------------------------------------------------------
__global__ __launch_bounds__(256) void combine_kernel(float* __restrict__ out)
{
    __shared__ float cI[16];
    const long row0 = (long)blockIdx.x * 16;
    const int tid = threadIdx.x;
    if (tid < 16) {
        long r = row0 + tid;
        cI[tid] = 1.f / (g_l0[r] + g_l1[r]);
    }
    __syncthreads();
    long base = row0 * 16 + tid;
    float4 a = ((const float4*)g_O0)[base];
    float4 c = ((const float4*)g_O1)[base];
    float inv = cI[tid >> 4];
    float4 o;
    o.x = (a.x + c.x) * inv;
    o.y = (a.y + c.y) * inv;
    o.z = (a.z + c.z) * inv;
    o.w = (a.w + c.w) * inv;
    ((float4*)out)[base] = o;
}

extern "C" void kernel_launch(void* const* d_in, const int* in_sizes, int n_in,
                              void* d_out, int out_size)
{
    const float* x  = (const float*)d_in[0];
    const float* Wk = (const float*)d_in[1];
    const float* Wq = (const float*)d_in[2];
    const float* Wv = (const float*)d_in[3];
    float* out = (float*)d_out;

    prepw_kernel<<<96, 256>>>(Wk, Wq, Wv);

    cudaFuncSetAttribute(proj_kernel,
                         cudaFuncAttributeMaxDynamicSharedMemorySize, PSM);
    proj_kernel<<<256, 256, PSM>>>(x);

    cudaFuncSetAttribute(attn_kernel,
                         cudaFuncAttributeMaxDynamicSharedMemorySize, ASM);
    attn_kernel<<<256, 256, ASM>>>();

    combine_kernel<<<NR / 16, 256>>>(out);
}